// round 4
// baseline (speedup 1.0000x reference)
#include <cuda_runtime.h>
#include <cuda_bf16.h>
#include <math.h>

// -------- scratch (static device globals; no allocation anywhere) ----------
#define CAND_CAP   (1 << 20)
#define SMEM_CAND  4096
#define PTS        8                        // points per thread in filter
__device__ float2 g_cand[CAND_CAP];  // .x = d2, .y = __int_as_float(index)
__device__ int    g_count;
__device__ int    g_done_s;          // sample-kernel done counter (returns to 0)
__device__ int    g_done_f;          // filter-kernel done counter (returns to 0)
__device__ float  g_thresh;          // d2 threshold (<= true 16th-largest d2)
__device__ float  g_pi[3];
__device__ float  g_bmax[256];       // per-chunk maxima

// ---------------------------------------------------------------------------
// Kernel 1 (sample + threshold): 256 blocks; block b computes max d^2 over a
// disjoint 1024-point chunk. Last block rank-selects the 16th-largest chunk
// max IN SHARED MEMORY (fix for R3's 5us of serial global scans). Threshold
// is provably <= global 16th-largest d^2 (16 distinct chunks hold >= it).
// ---------------------------------------------------------------------------
__global__ void k_sample(const float* __restrict__ P, const int* __restrict__ ip, int N)
{
    __shared__ float swarp[8];
    __shared__ float sv[256];
    __shared__ int   s_last;
    __shared__ int   s_thr_bits;
    const int b = blockIdx.x, t = threadIdx.x;
    if (b == 0 && t == 0) g_count = 0;

    const int i = *ip;
    const float px = P[6 * i + 0];
    const float py = P[6 * i + 1];
    const float pz = P[6 * i + 2];
    if (b == 0 && t < 3) g_pi[t] = P[6 * i + t];

    long long start = (long long)b * ((long long)N / 256);
    start &= ~1LL;
    if (start + 1024 > N) start = ((long long)N - 1024) & ~1LL;
    if (start < 0) start = 0;

    const float4* __restrict__ Pv = (const float4*)(P + start * 6);
    float m = -1.0f;
    #pragma unroll
    for (int u = 0; u < 2; u++) {
        const int q = 2 * t + u;            // pair id 0..511
        const float4 a  = Pv[3 * q + 0];
        const float4 bq = Pv[3 * q + 1];
        const float4 c  = Pv[3 * q + 2];
        { const float dx = a.x  - px, dy = a.y  - py, dz = a.z - pz; m = fmaxf(m, dx*dx + dy*dy + dz*dz); }
        { const float dx = bq.z - px, dy = bq.w - py, dz = c.x - pz; m = fmaxf(m, dx*dx + dy*dy + dz*dz); }
    }
    #pragma unroll
    for (int s = 16; s > 0; s >>= 1)
        m = fmaxf(m, __shfl_xor_sync(0xffffffffu, m, s));
    if ((t & 31) == 0) swarp[t >> 5] = m;
    __syncthreads();
    if (t == 0) {
        float mm = swarp[0];
        #pragma unroll
        for (int w = 1; w < 8; w++) mm = fmaxf(mm, swarp[w]);
        g_bmax[b] = mm;
        __threadfence();
        const int done = atomicAdd(&g_done_s, 1);
        s_last = (done == 255);
        s_thr_bits = 0;
    }
    __syncthreads();

    if (s_last) {
        __threadfence();                 // acquire side
        sv[t] = g_bmax[t];               // one global load per thread
        __syncthreads();
        const float my = sv[t];
        int g = 0;
        #pragma unroll 16
        for (int q = 0; q < 256; q++) g += (sv[q] > my) ? 1 : 0;
        if (g >= 15) atomicMax(&s_thr_bits, __float_as_int(my));  // d2 >= 0
        __syncthreads();
        if (t == 0) { g_thresh = __int_as_float(s_thr_bits); g_done_s = 0; }
    }
}

// ---------------------------------------------------------------------------
// Kernel 2 (filter + fused top-16 + epilogue): streaming filter, 8 pts/thread
// via 12 independent float4 loads. Last block to finish performs the exact
// top-16 select (packed 64-bit keys: (bits(sqrt(d2))<<32)|~idx, max-reduce ==
// (d desc, idx asc), matching jax.lax.top_k ties) and the affine epilogue.
// ---------------------------------------------------------------------------
__global__ void k_filter(const float* __restrict__ P,
                         const float* __restrict__ W,   // (3,10) row-major
                         const float* __restrict__ bb,  // (3,)
                         float* __restrict__ out,       // (16,6)
                         int N, int nblocks)
{
    __shared__ unsigned long long keys[SMEM_CAND];       // 32 KB
    __shared__ unsigned long long swarp[8];
    __shared__ unsigned long long s_win;
    __shared__ int sel[16];
    __shared__ int s_last;

    const int t = threadIdx.x;
    const int p = blockIdx.x * blockDim.x + t;
    const int j0 = PTS * p;

    const float px = g_pi[0], py = g_pi[1], pz = g_pi[2];
    const float thr = g_thresh;

    if (j0 + PTS - 1 < N) {
        const float4* __restrict__ Pv = (const float4*)P;
        const long long base = (long long)p * (3 * PTS / 2);   // 12 float4 per thread
        float4 f[12];
        #pragma unroll
        for (int q = 0; q < 12; q++) f[q] = Pv[base + q];

        #pragma unroll
        for (int q = 0; q < 4; q++) {                          // 4 pairs of points
            const float4 a  = f[3 * q + 0];
            const float4 bq = f[3 * q + 1];
            const float4 c  = f[3 * q + 2];
            {
                const float dx = a.x - px, dy = a.y - py, dz = a.z - pz;
                const float d2 = dx * dx + dy * dy + dz * dz;
                if (d2 >= thr) {
                    const int pos = atomicAdd(&g_count, 1);
                    if (pos < CAND_CAP) g_cand[pos] = make_float2(d2, __int_as_float(j0 + 2 * q));
                }
            }
            {
                const float dx = bq.z - px, dy = bq.w - py, dz = c.x - pz;
                const float d2 = dx * dx + dy * dy + dz * dz;
                if (d2 >= thr) {
                    const int pos = atomicAdd(&g_count, 1);
                    if (pos < CAND_CAP) g_cand[pos] = make_float2(d2, __int_as_float(j0 + 2 * q + 1));
                }
            }
        }
    } else if (j0 < N) {
        for (int j = j0; j < N; j++) {
            const float dx = P[6 * j + 0] - px;
            const float dy = P[6 * j + 1] - py;
            const float dz = P[6 * j + 2] - pz;
            const float d2 = dx * dx + dy * dy + dz * dz;
            if (d2 >= thr) {
                const int pos = atomicAdd(&g_count, 1);
                if (pos < CAND_CAP) g_cand[pos] = make_float2(d2, __int_as_float(j));
            }
        }
    }

    // ---- completion protocol ----
    __threadfence();
    __syncthreads();
    if (t == 0) {
        const int done = atomicAdd(&g_done_f, 1);
        s_last = (done == nblocks - 1);
    }
    __syncthreads();
    if (!s_last) return;

    // ---- last block: exact top-16 + epilogue ----
    __threadfence();                     // acquire: see all g_cand writes
    int cnt = g_count;
    if (cnt > SMEM_CAND) cnt = SMEM_CAND;

    for (int q = t; q < cnt; q += 256) {
        const float2 cv = g_cand[q];
        const unsigned int db = __float_as_uint(sqrtf(cv.x));   // d >= 0: bits ordered
        const unsigned int ik = ~(unsigned int)__float_as_int(cv.y);
        keys[q] = ((unsigned long long)db << 32) | ik;
    }
    __syncthreads();

    for (int r = 0; r < 16; r++) {
        unsigned long long mk = 0; int mpos = -1;
        for (int q = t; q < cnt; q += 256) {
            const unsigned long long k = keys[q];
            if (k > mk) { mk = k; mpos = q; }
        }
        unsigned long long wk = mk;
        #pragma unroll
        for (int s = 16; s > 0; s >>= 1) {
            const unsigned long long o = __shfl_xor_sync(0xffffffffu, wk, s);
            if (o > wk) wk = o;
        }
        if ((t & 31) == 0) swarp[t >> 5] = wk;
        __syncthreads();
        if (t < 8) {
            unsigned long long v = swarp[t];
            #pragma unroll
            for (int s = 4; s > 0; s >>= 1) {
                const unsigned long long o = __shfl_xor_sync(0xffu, v, s);
                if (o > v) v = o;
            }
            if (t == 0) s_win = v;
        }
        __syncthreads();
        const unsigned long long win = s_win;
        if (mk == win && mpos >= 0) keys[mpos] = 0ULL;   // unique owner removes it
        if (t == 0) sel[r] = (int)(~(unsigned int)(win & 0xFFFFFFFFULL));
        __syncthreads();
    }

    if (t < 16) {
        const int idx = sel[t];
        const float nx = P[6 * idx + 0];
        const float ny = P[6 * idx + 1];
        const float nz = P[6 * idx + 2];
        const float dx = px - nx, dy = py - ny, dz = pz - nz;
        const float dist = sqrtf(dx * dx + dy * dy + dz * dz);

        float feat[10] = {px, py, pz, nx, ny, nz, dx, dy, dz, dist};

        out[6 * t + 0] = nx;
        out[6 * t + 1] = ny;
        out[6 * t + 2] = nz;
        #pragma unroll
        for (int c = 0; c < 3; c++) {
            float acc = bb[c];
            #pragma unroll
            for (int j = 0; j < 10; j++)
                acc += feat[j] * W[c * 10 + j];
            out[6 * t + 3 + c] = acc;
        }
    }
    if (t == 0) g_done_f = 0;            // restore invariant for next replay
}

// ---------------------------------------------------------------------------
extern "C" void kernel_launch(void* const* d_in, const int* in_sizes, int n_in,
                              void* d_out, int out_size)
{
    const float* P  = (const float*)d_in[0];
    const float* W  = (const float*)d_in[1];
    const float* b  = (const float*)d_in[2];
    const int*   ip = (const int*)d_in[3];
    float* out = (float*)d_out;

    const int N = in_sizes[0] / 6;

    k_sample<<<256, 256>>>(P, ip, N);

    const int ptsPerBlock = PTS * 256;
    const int nblocks = (N + ptsPerBlock - 1) / ptsPerBlock;
    k_filter<<<nblocks, 256>>>(P, W, b, out, N, nblocks);
}

// round 5
// speedup vs baseline: 1.6554x; 1.6554x over previous
#include <cuda_runtime.h>
#include <cuda_bf16.h>
#include <math.h>

// -------- scratch (static device globals; no allocation anywhere) ----------
#define CAND_CAP   (1 << 20)
#define SMEM_CAND  4096
__device__ float2 g_cand[CAND_CAP];  // .x = d2, .y = __int_as_float(index)
__device__ int    g_count;
__device__ int    g_done_s;          // sample-kernel done counter (returns to 0)
__device__ int    g_done_f;          // filter-kernel done counter (returns to 0)
__device__ float  g_thresh;          // d2 threshold (<= true 16th-largest d2)
__device__ float  g_pi[3];
__device__ float  g_bmax[256];       // per-chunk maxima

// ---------------------------------------------------------------------------
// Kernel 1 (sample + threshold): 256 blocks; block b computes max d^2 over a
// disjoint 1024-point chunk. Last block rank-selects the 16th-largest chunk
// max in shared memory. Threshold provably <= global 16th-largest d^2.
// ---------------------------------------------------------------------------
__global__ void k_sample(const float* __restrict__ P, const int* __restrict__ ip, int N)
{
    __shared__ float swarp[8];
    __shared__ float sv[256];
    __shared__ int   s_last;
    __shared__ int   s_thr_bits;
    const int b = blockIdx.x, t = threadIdx.x;
    if (b == 0 && t == 0) g_count = 0;

    const int i = *ip;
    const float px = P[6 * i + 0];
    const float py = P[6 * i + 1];
    const float pz = P[6 * i + 2];
    if (b == 0 && t < 3) g_pi[t] = P[6 * i + t];

    long long start = (long long)b * ((long long)N / 256);
    start &= ~1LL;
    if (start + 1024 > N) start = ((long long)N - 1024) & ~1LL;
    if (start < 0) start = 0;

    const float4* __restrict__ Pv = (const float4*)(P + start * 6);
    float m = -1.0f;
    #pragma unroll
    for (int u = 0; u < 2; u++) {
        const int q = 2 * t + u;            // pair id 0..511
        const float4 a  = Pv[3 * q + 0];
        const float4 bq = Pv[3 * q + 1];
        const float4 c  = Pv[3 * q + 2];
        { const float dx = a.x  - px, dy = a.y  - py, dz = a.z - pz; m = fmaxf(m, dx*dx + dy*dy + dz*dz); }
        { const float dx = bq.z - px, dy = bq.w - py, dz = c.x - pz; m = fmaxf(m, dx*dx + dy*dy + dz*dz); }
    }
    #pragma unroll
    for (int s = 16; s > 0; s >>= 1)
        m = fmaxf(m, __shfl_xor_sync(0xffffffffu, m, s));
    if ((t & 31) == 0) swarp[t >> 5] = m;
    __syncthreads();
    if (t == 0) {
        float mm = swarp[0];
        #pragma unroll
        for (int w = 1; w < 8; w++) mm = fmaxf(mm, swarp[w]);
        g_bmax[b] = mm;
        __threadfence();
        const int done = atomicAdd(&g_done_s, 1);
        s_last = (done == 255);
        s_thr_bits = 0;
    }
    __syncthreads();

    if (s_last) {
        __threadfence();
        sv[t] = g_bmax[t];
        __syncthreads();
        const float my = sv[t];
        int g = 0;
        #pragma unroll 16
        for (int q = 0; q < 256; q++) g += (sv[q] > my) ? 1 : 0;
        if (g >= 15) atomicMax(&s_thr_bits, __float_as_int(my));  // d2 >= 0
        __syncthreads();
        if (t == 0) { g_thresh = __int_as_float(s_thr_bits); g_done_s = 0; }
    }
}

// ---------------------------------------------------------------------------
// Kernel 2 (filter + fused top-16 + epilogue): 4 points/thread via six NAMED
// float4 registers (R4's f[12] array spilled to local memory -> 107us; this
// is the proven R3 register shape). Last block to finish does the exact
// top-16 (packed keys: (bits(sqrt(d2))<<32)|~idx) and the affine epilogue.
// ---------------------------------------------------------------------------
__global__ void k_filter(const float* __restrict__ P,
                         const float* __restrict__ W,   // (3,10) row-major
                         const float* __restrict__ bb,  // (3,)
                         float* __restrict__ out,       // (16,6)
                         int N, int nblocks)
{
    __shared__ unsigned long long keys[SMEM_CAND];       // 32 KB
    __shared__ unsigned long long swarp[8];
    __shared__ unsigned long long s_win;
    __shared__ int sel[16];
    __shared__ int s_last;

    const int t = threadIdx.x;
    const int p = blockIdx.x * blockDim.x + t;
    const int j0 = 4 * p;

    const float px = g_pi[0], py = g_pi[1], pz = g_pi[2];
    const float thr = g_thresh;

    if (j0 + 3 < N) {
        const float4* __restrict__ Pv = (const float4*)P;
        const float4 g0 = Pv[6 * p + 0];
        const float4 g1 = Pv[6 * p + 1];
        const float4 g2 = Pv[6 * p + 2];
        const float4 g3 = Pv[6 * p + 3];
        const float4 g4 = Pv[6 * p + 4];
        const float4 g5 = Pv[6 * p + 5];

        float d2a, d2b, d2c, d2d;
        { const float dx = g0.x - px, dy = g0.y - py, dz = g0.z - pz; d2a = dx*dx + dy*dy + dz*dz; }
        { const float dx = g1.z - px, dy = g1.w - py, dz = g2.x - pz; d2b = dx*dx + dy*dy + dz*dz; }
        { const float dx = g3.x - px, dy = g3.y - py, dz = g3.z - pz; d2c = dx*dx + dy*dy + dz*dz; }
        { const float dx = g4.z - px, dy = g4.w - py, dz = g5.x - pz; d2d = dx*dx + dy*dy + dz*dz; }

        if (d2a >= thr) { const int pos = atomicAdd(&g_count, 1); if (pos < CAND_CAP) g_cand[pos] = make_float2(d2a, __int_as_float(j0 + 0)); }
        if (d2b >= thr) { const int pos = atomicAdd(&g_count, 1); if (pos < CAND_CAP) g_cand[pos] = make_float2(d2b, __int_as_float(j0 + 1)); }
        if (d2c >= thr) { const int pos = atomicAdd(&g_count, 1); if (pos < CAND_CAP) g_cand[pos] = make_float2(d2c, __int_as_float(j0 + 2)); }
        if (d2d >= thr) { const int pos = atomicAdd(&g_count, 1); if (pos < CAND_CAP) g_cand[pos] = make_float2(d2d, __int_as_float(j0 + 3)); }
    } else if (j0 < N) {
        for (int j = j0; j < N; j++) {
            const float dx = P[6 * j + 0] - px;
            const float dy = P[6 * j + 1] - py;
            const float dz = P[6 * j + 2] - pz;
            const float d2 = dx * dx + dy * dy + dz * dz;
            if (d2 >= thr) {
                const int pos = atomicAdd(&g_count, 1);
                if (pos < CAND_CAP) g_cand[pos] = make_float2(d2, __int_as_float(j));
            }
        }
    }

    // ---- completion protocol ----
    __threadfence();
    __syncthreads();
    if (t == 0) {
        const int done = atomicAdd(&g_done_f, 1);
        s_last = (done == nblocks - 1);
    }
    __syncthreads();
    if (!s_last) return;

    // ---- last block: exact top-16 + epilogue ----
    __threadfence();                     // acquire: see all g_cand writes
    int cnt = g_count;
    if (cnt > SMEM_CAND) cnt = SMEM_CAND;

    for (int q = t; q < cnt; q += 256) {
        const float2 cv = g_cand[q];
        const unsigned int db = __float_as_uint(sqrtf(cv.x));   // d >= 0: bits ordered
        const unsigned int ik = ~(unsigned int)__float_as_int(cv.y);
        keys[q] = ((unsigned long long)db << 32) | ik;
    }
    __syncthreads();

    for (int r = 0; r < 16; r++) {
        unsigned long long mk = 0; int mpos = -1;
        for (int q = t; q < cnt; q += 256) {
            const unsigned long long k = keys[q];
            if (k > mk) { mk = k; mpos = q; }
        }
        unsigned long long wk = mk;
        #pragma unroll
        for (int s = 16; s > 0; s >>= 1) {
            const unsigned long long o = __shfl_xor_sync(0xffffffffu, wk, s);
            if (o > wk) wk = o;
        }
        if ((t & 31) == 0) swarp[t >> 5] = wk;
        __syncthreads();
        if (t < 8) {
            unsigned long long v = swarp[t];
            #pragma unroll
            for (int s = 4; s > 0; s >>= 1) {
                const unsigned long long o = __shfl_xor_sync(0xffu, v, s);
                if (o > v) v = o;
            }
            if (t == 0) s_win = v;
        }
        __syncthreads();
        const unsigned long long win = s_win;
        if (mk == win && mpos >= 0) keys[mpos] = 0ULL;   // unique owner removes it
        if (t == 0) sel[r] = (int)(~(unsigned int)(win & 0xFFFFFFFFULL));
        __syncthreads();
    }

    if (t < 16) {
        const int idx = sel[t];
        const float nx = P[6 * idx + 0];
        const float ny = P[6 * idx + 1];
        const float nz = P[6 * idx + 2];
        const float dx = px - nx, dy = py - ny, dz = pz - nz;
        const float dist = sqrtf(dx * dx + dy * dy + dz * dz);

        float feat[10] = {px, py, pz, nx, ny, nz, dx, dy, dz, dist};

        out[6 * t + 0] = nx;
        out[6 * t + 1] = ny;
        out[6 * t + 2] = nz;
        #pragma unroll
        for (int c = 0; c < 3; c++) {
            float acc = bb[c];
            #pragma unroll
            for (int j = 0; j < 10; j++)
                acc += feat[j] * W[c * 10 + j];
            out[6 * t + 3 + c] = acc;
        }
    }
    if (t == 0) g_done_f = 0;            // restore invariant for next replay
}

// ---------------------------------------------------------------------------
extern "C" void kernel_launch(void* const* d_in, const int* in_sizes, int n_in,
                              void* d_out, int out_size)
{
    const float* P  = (const float*)d_in[0];
    const float* W  = (const float*)d_in[1];
    const float* b  = (const float*)d_in[2];
    const int*   ip = (const int*)d_in[3];
    float* out = (float*)d_out;

    const int N = in_sizes[0] / 6;

    k_sample<<<256, 256>>>(P, ip, N);

    const int ptsPerBlock = 4 * 256;
    const int nblocks = (N + ptsPerBlock - 1) / ptsPerBlock;
    k_filter<<<nblocks, 256>>>(P, W, b, out, N, nblocks);
}

// round 6
// speedup vs baseline: 2.2667x; 1.3692x over previous
#include <cuda_runtime.h>
#include <cuda_bf16.h>
#include <math.h>

// -------- scratch (static device globals; no allocation anywhere) ----------
#define CAND_CAP   (1 << 20)
#define SMEM_CAND  4096
__device__ float2 g_cand[CAND_CAP];  // .x = d2, .y = __int_as_float(index)
__device__ int    g_count;
__device__ int    g_done_s;          // sample-kernel done counter (returns to 0)
__device__ float  g_thresh;          // d2 threshold (<= true 16th-largest d2)
__device__ float  g_pi[3];
__device__ float  g_bmax[256];       // per-chunk maxima

// ---------------------------------------------------------------------------
// Kernel 1 (sample + threshold): 256 blocks; block b computes max d^2 over a
// disjoint 1024-point chunk. Last block rank-selects the 16th-largest chunk
// max in shared memory. Threshold provably <= global 16th-largest d^2.
// ---------------------------------------------------------------------------
__global__ void k_sample(const float* __restrict__ P, const int* __restrict__ ip, int N)
{
    __shared__ float swarp[8];
    __shared__ float sv[256];
    __shared__ int   s_last;
    __shared__ int   s_thr_bits;
    const int b = blockIdx.x, t = threadIdx.x;
    if (b == 0 && t == 0) g_count = 0;

    const int i = *ip;
    const float px = P[6 * i + 0];
    const float py = P[6 * i + 1];
    const float pz = P[6 * i + 2];
    if (b == 0 && t < 3) g_pi[t] = P[6 * i + t];

    long long start = (long long)b * ((long long)N / 256);
    start &= ~1LL;
    if (start + 1024 > N) start = ((long long)N - 1024) & ~1LL;
    if (start < 0) start = 0;

    const float4* __restrict__ Pv = (const float4*)(P + start * 6);
    float m = -1.0f;
    #pragma unroll
    for (int u = 0; u < 2; u++) {
        const int q = 2 * t + u;            // pair id 0..511
        const float4 a  = Pv[3 * q + 0];
        const float4 bq = Pv[3 * q + 1];
        const float4 c  = Pv[3 * q + 2];
        { const float dx = a.x  - px, dy = a.y  - py, dz = a.z - pz; m = fmaxf(m, dx*dx + dy*dy + dz*dz); }
        { const float dx = bq.z - px, dy = bq.w - py, dz = c.x - pz; m = fmaxf(m, dx*dx + dy*dy + dz*dz); }
    }
    #pragma unroll
    for (int s = 16; s > 0; s >>= 1)
        m = fmaxf(m, __shfl_xor_sync(0xffffffffu, m, s));
    if ((t & 31) == 0) swarp[t >> 5] = m;
    __syncthreads();
    if (t == 0) {
        float mm = swarp[0];
        #pragma unroll
        for (int w = 1; w < 8; w++) mm = fmaxf(mm, swarp[w]);
        g_bmax[b] = mm;
        __threadfence();
        const int done = atomicAdd(&g_done_s, 1);
        s_last = (done == 255);
        s_thr_bits = 0;
    }
    __syncthreads();

    if (s_last) {
        __threadfence();
        sv[t] = g_bmax[t];
        __syncthreads();
        const float my = sv[t];
        int g = 0;
        #pragma unroll 16
        for (int q = 0; q < 256; q++) g += (sv[q] > my) ? 1 : 0;
        if (g >= 15) atomicMax(&s_thr_bits, __float_as_int(my));  // d2 >= 0
        __syncthreads();
        if (t == 0) { g_thresh = __int_as_float(s_thr_bits); g_done_s = 0; }
    }
}

// ---------------------------------------------------------------------------
// Kernel 2: LEAN streaming filter (the R2/R3 shape that ran ~23us): 4 points
// per thread via six named float4 registers, no smem, no fences, no tail.
// Survivors (d2 >= thresh, ~500 of 8M) appended via rare atomics.
// ---------------------------------------------------------------------------
__global__ void k_filter(const float* __restrict__ P, int N)
{
    const int p = blockIdx.x * blockDim.x + threadIdx.x;
    const int j0 = 4 * p;
    if (j0 >= N) return;

    const float px = g_pi[0], py = g_pi[1], pz = g_pi[2];
    const float thr = g_thresh;

    if (j0 + 3 < N) {
        const float4* __restrict__ Pv = (const float4*)P;
        const float4 g0 = Pv[6 * p + 0];
        const float4 g1 = Pv[6 * p + 1];
        const float4 g2 = Pv[6 * p + 2];
        const float4 g3 = Pv[6 * p + 3];
        const float4 g4 = Pv[6 * p + 4];
        const float4 g5 = Pv[6 * p + 5];

        float d2a, d2b, d2c, d2d;
        { const float dx = g0.x - px, dy = g0.y - py, dz = g0.z - pz; d2a = dx*dx + dy*dy + dz*dz; }
        { const float dx = g1.z - px, dy = g1.w - py, dz = g2.x - pz; d2b = dx*dx + dy*dy + dz*dz; }
        { const float dx = g3.x - px, dy = g3.y - py, dz = g3.z - pz; d2c = dx*dx + dy*dy + dz*dz; }
        { const float dx = g4.z - px, dy = g4.w - py, dz = g5.x - pz; d2d = dx*dx + dy*dy + dz*dz; }

        if (d2a >= thr) { const int pos = atomicAdd(&g_count, 1); if (pos < CAND_CAP) g_cand[pos] = make_float2(d2a, __int_as_float(j0 + 0)); }
        if (d2b >= thr) { const int pos = atomicAdd(&g_count, 1); if (pos < CAND_CAP) g_cand[pos] = make_float2(d2b, __int_as_float(j0 + 1)); }
        if (d2c >= thr) { const int pos = atomicAdd(&g_count, 1); if (pos < CAND_CAP) g_cand[pos] = make_float2(d2c, __int_as_float(j0 + 2)); }
        if (d2d >= thr) { const int pos = atomicAdd(&g_count, 1); if (pos < CAND_CAP) g_cand[pos] = make_float2(d2d, __int_as_float(j0 + 3)); }
    } else {
        for (int j = j0; j < N; j++) {
            const float dx = P[6 * j + 0] - px;
            const float dy = P[6 * j + 1] - py;
            const float dz = P[6 * j + 2] - pz;
            const float d2 = dx * dx + dy * dy + dz * dz;
            if (d2 >= thr) {
                const int pos = atomicAdd(&g_count, 1);
                if (pos < CAND_CAP) g_cand[pos] = make_float2(d2, __int_as_float(j));
            }
        }
    }
}

// ---------------------------------------------------------------------------
// Kernel 3: exact top-16 via packed 64-bit keys.
//   key = (bits(sqrt(d2)) << 32) | ~idx  -> max-reduce == (d desc, idx asc),
// matching jax.lax.top_k tie semantics. Then the affine epilogue.
// ---------------------------------------------------------------------------
__global__ void k_final(const float* __restrict__ P,
                        const float* __restrict__ W,   // (3,10) row-major
                        const float* __restrict__ bb,  // (3,)
                        float* __restrict__ out)       // (16,6)
{
    __shared__ unsigned long long keys[SMEM_CAND];
    __shared__ unsigned long long swarp[8];
    __shared__ unsigned long long s_win;
    __shared__ int sel[16];

    const int t = threadIdx.x;
    int cnt = g_count;
    if (cnt > SMEM_CAND) cnt = SMEM_CAND;   // survivors ~500; cap is 8x margin

    for (int q = t; q < cnt; q += 256) {
        const float2 cv = g_cand[q];
        const unsigned int db = __float_as_uint(sqrtf(cv.x));   // d >= 0: bits ordered
        const unsigned int ik = ~(unsigned int)__float_as_int(cv.y);
        keys[q] = ((unsigned long long)db << 32) | ik;
    }
    __syncthreads();

    for (int r = 0; r < 16; r++) {
        unsigned long long mk = 0; int mpos = -1;
        for (int q = t; q < cnt; q += 256) {
            const unsigned long long k = keys[q];
            if (k > mk) { mk = k; mpos = q; }
        }
        unsigned long long wk = mk;
        #pragma unroll
        for (int s = 16; s > 0; s >>= 1) {
            const unsigned long long o = __shfl_xor_sync(0xffffffffu, wk, s);
            if (o > wk) wk = o;
        }
        if ((t & 31) == 0) swarp[t >> 5] = wk;
        __syncthreads();
        if (t < 8) {
            unsigned long long v = swarp[t];
            #pragma unroll
            for (int s = 4; s > 0; s >>= 1) {
                const unsigned long long o = __shfl_xor_sync(0xffu, v, s);
                if (o > v) v = o;
            }
            if (t == 0) s_win = v;
        }
        __syncthreads();
        const unsigned long long win = s_win;
        if (mk == win && mpos >= 0) keys[mpos] = 0ULL;   // unique owner removes it
        if (t == 0) sel[r] = (int)(~(unsigned int)(win & 0xFFFFFFFFULL));
        __syncthreads();
    }

    if (t < 16) {
        const float px = g_pi[0], py = g_pi[1], pz = g_pi[2];
        const int idx = sel[t];
        const float nx = P[6 * idx + 0];
        const float ny = P[6 * idx + 1];
        const float nz = P[6 * idx + 2];
        const float dx = px - nx, dy = py - ny, dz = pz - nz;
        const float dist = sqrtf(dx * dx + dy * dy + dz * dz);

        float feat[10] = {px, py, pz, nx, ny, nz, dx, dy, dz, dist};

        out[6 * t + 0] = nx;
        out[6 * t + 1] = ny;
        out[6 * t + 2] = nz;
        #pragma unroll
        for (int c = 0; c < 3; c++) {
            float acc = bb[c];
            #pragma unroll
            for (int j = 0; j < 10; j++)
                acc += feat[j] * W[c * 10 + j];
            out[6 * t + 3 + c] = acc;
        }
    }
}

// ---------------------------------------------------------------------------
extern "C" void kernel_launch(void* const* d_in, const int* in_sizes, int n_in,
                              void* d_out, int out_size)
{
    const float* P  = (const float*)d_in[0];
    const float* W  = (const float*)d_in[1];
    const float* b  = (const float*)d_in[2];
    const int*   ip = (const int*)d_in[3];
    float* out = (float*)d_out;

    const int N = in_sizes[0] / 6;

    k_sample<<<256, 256>>>(P, ip, N);

    const int blocks = (N + 1023) / 1024;   // 4 points per thread
    k_filter<<<blocks, 256>>>(P, N);

    k_final<<<1, 256>>>(P, W, b, out);
}

// round 10
// speedup vs baseline: 2.2784x; 1.0052x over previous
#include <cuda_runtime.h>
#include <cuda_bf16.h>
#include <math.h>

// -------- scratch (static device globals; no allocation anywhere) ----------
#define CAND_CAP   (1 << 20)
#define SMEM_CAND  4096
#define SBLK       1024                  // sample blocks
__device__ float2 g_cand[CAND_CAP];  // .x = d2, .y = __int_as_float(index)
__device__ int    g_count;
__device__ int    g_done_s;          // sample-kernel done counter (returns to 0)
__device__ float  g_thresh;          // d2 threshold (<= true 16th-largest d2)
__device__ float  g_pi[3];
__device__ float  g_bmax[SBLK];      // per-chunk maxima

// ---------------------------------------------------------------------------
// Kernel 1 (sample + threshold): 1024 blocks x 256 threads; block b computes
// max d^2 over a disjoint 512-point chunk (1 pair/thread, 3 float4 loads).
// Full-chip single wave (vs R6's 256 blocks = 1.7/SM, latency-bound, 9us).
// Last block max-groups the 1024 maxima 4->1 (disjoint 2048-pt sets) and
// rank-selects the 16th largest of the 256 grouped maxima in smem.
// Threshold provably <= global 16th-largest d^2.
// ---------------------------------------------------------------------------
__global__ void k_sample(const float* __restrict__ P, const int* __restrict__ ip, int N)
{
    __shared__ float swarp[8];
    __shared__ float sv[256];
    __shared__ int   s_last;
    __shared__ int   s_thr_bits;
    const int b = blockIdx.x, t = threadIdx.x;
    if (b == 0 && t == 0) g_count = 0;

    const int i = *ip;
    const float px = P[6 * i + 0];
    const float py = P[6 * i + 1];
    const float pz = P[6 * i + 2];
    if (b == 0 && t < 3) g_pi[t] = P[6 * i + t];

    long long start = (long long)b * ((long long)N / SBLK);
    start &= ~1LL;
    if (start + 512 > N) start = ((long long)N - 512) & ~1LL;
    if (start < 0) start = 0;

    // pair t: points start+2t, start+2t+1 -> float4s 3t..3t+2
    const float4* __restrict__ Pv = (const float4*)(P + start * 6);
    float m = -1.0f;
    {
        const float4 a  = Pv[3 * t + 0];
        const float4 bq = Pv[3 * t + 1];
        const float4 c  = Pv[3 * t + 2];
        { const float dx = a.x  - px, dy = a.y  - py, dz = a.z - pz; m = fmaxf(m, dx*dx + dy*dy + dz*dz); }
        { const float dx = bq.z - px, dy = bq.w - py, dz = c.x - pz; m = fmaxf(m, dx*dx + dy*dy + dz*dz); }
    }
    #pragma unroll
    for (int s = 16; s > 0; s >>= 1)
        m = fmaxf(m, __shfl_xor_sync(0xffffffffu, m, s));
    if ((t & 31) == 0) swarp[t >> 5] = m;
    __syncthreads();
    if (t == 0) {
        float mm = swarp[0];
        #pragma unroll
        for (int w = 1; w < 8; w++) mm = fmaxf(mm, swarp[w]);
        g_bmax[b] = mm;
        __threadfence();
        const int done = atomicAdd(&g_done_s, 1);
        s_last = (done == SBLK - 1);
        s_thr_bits = 0;
    }
    __syncthreads();

    if (s_last) {
        __threadfence();
        // group 4 consecutive chunk maxima -> 256 values (disjoint 2048-pt sets)
        const float v0 = g_bmax[4 * t + 0];
        const float v1 = g_bmax[4 * t + 1];
        const float v2 = g_bmax[4 * t + 2];
        const float v3 = g_bmax[4 * t + 3];
        sv[t] = fmaxf(fmaxf(v0, v1), fmaxf(v2, v3));
        __syncthreads();
        const float my = sv[t];
        int g = 0;
        #pragma unroll 16
        for (int q = 0; q < 256; q++) g += (sv[q] > my) ? 1 : 0;
        if (g >= 15) atomicMax(&s_thr_bits, __float_as_int(my));  // d2 >= 0
        __syncthreads();
        if (t == 0) { g_thresh = __int_as_float(s_thr_bits); g_done_s = 0; }
    }
}

// ---------------------------------------------------------------------------
// Kernel 2: LEAN streaming filter: 4 points/thread via six named float4
// registers, no smem, no fences. Survivors appended via rare atomics.
// ---------------------------------------------------------------------------
__global__ void k_filter(const float* __restrict__ P, int N)
{
    const int p = blockIdx.x * blockDim.x + threadIdx.x;
    const int j0 = 4 * p;
    if (j0 >= N) return;

    const float px = g_pi[0], py = g_pi[1], pz = g_pi[2];
    const float thr = g_thresh;

    if (j0 + 3 < N) {
        const float4* __restrict__ Pv = (const float4*)P;
        const float4 g0 = Pv[6 * p + 0];
        const float4 g1 = Pv[6 * p + 1];
        const float4 g2 = Pv[6 * p + 2];
        const float4 g3 = Pv[6 * p + 3];
        const float4 g4 = Pv[6 * p + 4];
        const float4 g5 = Pv[6 * p + 5];

        float d2a, d2b, d2c, d2d;
        { const float dx = g0.x - px, dy = g0.y - py, dz = g0.z - pz; d2a = dx*dx + dy*dy + dz*dz; }
        { const float dx = g1.z - px, dy = g1.w - py, dz = g2.x - pz; d2b = dx*dx + dy*dy + dz*dz; }
        { const float dx = g3.x - px, dy = g3.y - py, dz = g3.z - pz; d2c = dx*dx + dy*dy + dz*dz; }
        { const float dx = g4.z - px, dy = g4.w - py, dz = g5.x - pz; d2d = dx*dx + dy*dy + dz*dz; }

        if (d2a >= thr) { const int pos = atomicAdd(&g_count, 1); if (pos < CAND_CAP) g_cand[pos] = make_float2(d2a, __int_as_float(j0 + 0)); }
        if (d2b >= thr) { const int pos = atomicAdd(&g_count, 1); if (pos < CAND_CAP) g_cand[pos] = make_float2(d2b, __int_as_float(j0 + 1)); }
        if (d2c >= thr) { const int pos = atomicAdd(&g_count, 1); if (pos < CAND_CAP) g_cand[pos] = make_float2(d2c, __int_as_float(j0 + 2)); }
        if (d2d >= thr) { const int pos = atomicAdd(&g_count, 1); if (pos < CAND_CAP) g_cand[pos] = make_float2(d2d, __int_as_float(j0 + 3)); }
    } else {
        for (int j = j0; j < N; j++) {
            const float dx = P[6 * j + 0] - px;
            const float dy = P[6 * j + 1] - py;
            const float dz = P[6 * j + 2] - pz;
            const float d2 = dx * dx + dy * dy + dz * dz;
            if (d2 >= thr) {
                const int pos = atomicAdd(&g_count, 1);
                if (pos < CAND_CAP) g_cand[pos] = make_float2(d2, __int_as_float(j));
            }
        }
    }
}

// ---------------------------------------------------------------------------
// Kernel 3: exact top-16 via packed 64-bit keys.
//   key = (bits(sqrt(d2)) << 32) | ~idx  -> max-reduce == (d desc, idx asc),
// matching jax.lax.top_k tie semantics. Then the affine epilogue.
// ---------------------------------------------------------------------------
__global__ void k_final(const float* __restrict__ P,
                        const float* __restrict__ W,   // (3,10) row-major
                        const float* __restrict__ bb,  // (3,)
                        float* __restrict__ out)       // (16,6)
{
    __shared__ unsigned long long keys[SMEM_CAND];
    __shared__ unsigned long long swarp[8];
    __shared__ unsigned long long s_win;
    __shared__ int sel[16];

    const int t = threadIdx.x;
    int cnt = g_count;
    if (cnt > SMEM_CAND) cnt = SMEM_CAND;   // survivors ~450; cap is 9x margin

    for (int q = t; q < cnt; q += 256) {
        const float2 cv = g_cand[q];
        const unsigned int db = __float_as_uint(sqrtf(cv.x));   // d >= 0: bits ordered
        const unsigned int ik = ~(unsigned int)__float_as_int(cv.y);
        keys[q] = ((unsigned long long)db << 32) | ik;
    }
    __syncthreads();

    for (int r = 0; r < 16; r++) {
        unsigned long long mk = 0; int mpos = -1;
        for (int q = t; q < cnt; q += 256) {
            const unsigned long long k = keys[q];
            if (k > mk) { mk = k; mpos = q; }
        }
        unsigned long long wk = mk;
        #pragma unroll
        for (int s = 16; s > 0; s >>= 1) {
            const unsigned long long o = __shfl_xor_sync(0xffffffffu, wk, s);
            if (o > wk) wk = o;
        }
        if ((t & 31) == 0) swarp[t >> 5] = wk;
        __syncthreads();
        if (t < 8) {
            unsigned long long v = swarp[t];
            #pragma unroll
            for (int s = 4; s > 0; s >>= 1) {
                const unsigned long long o = __shfl_xor_sync(0xffu, v, s);
                if (o > v) v = o;
            }
            if (t == 0) s_win = v;
        }
        __syncthreads();
        const unsigned long long win = s_win;
        if (mk == win && mpos >= 0) keys[mpos] = 0ULL;   // unique owner removes it
        if (t == 0) sel[r] = (int)(~(unsigned int)(win & 0xFFFFFFFFULL));
        __syncthreads();
    }

    if (t < 16) {
        const float px = g_pi[0], py = g_pi[1], pz = g_pi[2];
        const int idx = sel[t];
        const float nx = P[6 * idx + 0];
        const float ny = P[6 * idx + 1];
        const float nz = P[6 * idx + 2];
        const float dx = px - nx, dy = py - ny, dz = pz - nz;
        const float dist = sqrtf(dx * dx + dy * dy + dz * dz);

        float feat[10] = {px, py, pz, nx, ny, nz, dx, dy, dz, dist};

        out[6 * t + 0] = nx;
        out[6 * t + 1] = ny;
        out[6 * t + 2] = nz;
        #pragma unroll
        for (int c = 0; c < 3; c++) {
            float acc = bb[c];
            #pragma unroll
            for (int j = 0; j < 10; j++)
                acc += feat[j] * W[c * 10 + j];
            out[6 * t + 3 + c] = acc;
        }
    }
}

// ---------------------------------------------------------------------------
extern "C" void kernel_launch(void* const* d_in, const int* in_sizes, int n_in,
                              void* d_out, int out_size)
{
    const float* P  = (const float*)d_in[0];
    const float* W  = (const float*)d_in[1];
    const float* b  = (const float*)d_in[2];
    const int*   ip = (const int*)d_in[3];
    float* out = (float*)d_out;

    const int N = in_sizes[0] / 6;

    k_sample<<<SBLK, 256>>>(P, ip, N);

    const int blocks = (N + 1023) / 1024;   // 4 points per thread
    k_filter<<<blocks, 256>>>(P, N);

    k_final<<<1, 256>>>(P, W, b, out);
}